// round 3
// baseline (speedup 1.0000x reference)
#include <cuda_runtime.h>
#include <math.h>
#include <stdint.h>

// Problem constants
#define CD    768
#define K9    6912        // 9 * 768
#define HGT   32
#define WID   32
#define NPIX  4096        // per level: 4*32*32
#define MTOT  20480       // 5 * 4096
#define WHK   1536        // head GEMM K (y | x concat)
#define WHN   384         // head GEMM padded N (3 tiles of 128)

// ---------------------------------------------------------------------------
// Scratch (device globals — allocation in kernel_launch is forbidden)
// ---------------------------------------------------------------------------
__device__ __align__(16) float g_A[(size_t)MTOT * K9];    // im2col, then re-used for sampled features (566 MB)
__device__ __align__(16) float g_om[(size_t)MTOT * CD];   // conv3x3 output (NHWC rows)
__device__ __align__(16) float g_y[(size_t)MTOT * CD];    // deform block output
__device__ __align__(16) float g_Wb[(size_t)K9 * CD];     // packed weights: Wb[(k*768+c)*768+o] = conv_w[o,c,k]
__device__ __align__(16) float g_Wh[5 * WHK * WHN];       // packed head weights [lev][k][n], zero padded
__device__ float g_off[MTOT * 18];                        // per pixel: dy0,dx0,dy1,dx1,...
__device__ float g_msm[MTOT * 9];                         // softmax(mask logits), pixel-major, k innermost
__device__ float g_scale[CD];
__device__ float g_shift[CD];

// ---------------------------------------------------------------------------
__device__ __forceinline__ const float* sel5(int i, const float* a, const float* b,
                                             const float* c, const float* d, const float* e) {
    switch (i) { case 0: return a; case 1: return b; case 2: return c; case 3: return d; default: return e; }
}

__device__ __forceinline__ float tf32r(float x) {
    float y;
    asm("cvt.rna.tf32.f32 %0, %1;" : "=f"(y) : "f"(x));
    return y;
}
__device__ __forceinline__ float4 tf32r4(float4 v) {
    v.x = tf32r(v.x); v.y = tf32r(v.y); v.z = tf32r(v.z); v.w = tf32r(v.w);
    return v;
}

// ---------------------------------------------------------------------------
// Pack conv weights into GEMM-B layout (used by BOTH big GEMMs)
// ---------------------------------------------------------------------------
__global__ void pack_kernel(const float* __restrict__ cw) {
    int i = blockIdx.x * 256 + threadIdx.x;
    if (i >= K9 * CD) return;
    int o = i % CD;
    int kc = i / CD;
    int c = kc % CD;
    int k = kc / CD;
    g_Wb[i] = cw[((size_t)o * CD + c) * 9 + k];
}

// Pack head weights: g_Wh[lev][k][n] = (k<768 ? wa[n][k] : wb[n][k-768]), 0 beyond ch or missing wb
__global__ void pack_head_kernel(const float* __restrict__ w1, const float* __restrict__ w2,
                                 const float* __restrict__ w3a, const float* __restrict__ w3b,
                                 const float* __restrict__ w4a, const float* __restrict__ w4b,
                                 const float* __restrict__ w5a, const float* __restrict__ w5b) {
    int i = blockIdx.x * 256 + threadIdx.x;
    if (i >= 5 * WHK * WHN) return;
    int lev = i / (WHK * WHN);
    int rem = i % (WHK * WHN);
    int k = rem / WHN;
    int n = rem % WHN;

    const int chs[5] = { 30, 100, 150, 220, 268 };
    const float* wa;
    const float* wb;
    switch (lev) {
        case 0: wa = w1;  wb = nullptr; break;
        case 1: wa = w2;  wb = nullptr; break;
        case 2: wa = w3a; wb = w3b;     break;
        case 3: wa = w4a; wb = w4b;     break;
        default: wa = w5a; wb = w5b;    break;
    }
    float v = 0.f;
    if (n < chs[lev]) {
        if (k < CD) v = wa[(size_t)n * CD + k];
        else if (wb != nullptr) v = wb[(size_t)n * CD + (k - CD)];
    }
    g_Wh[i] = v;
}

__global__ void bnprep_kernel(const float* __restrict__ g, const float* __restrict__ be,
                              const float* __restrict__ mu, const float* __restrict__ var) {
    int i = blockIdx.x * 256 + threadIdx.x;
    if (i < CD) {
        float inv = g[i] / sqrtf(var[i] + 1e-5f);
        g_scale[i] = inv;
        g_shift[i] = be[i] - mu[i] * inv;
    }
}

// ---------------------------------------------------------------------------
// im2col: g_A[m][k*768+c] = x_lev[n, h+ky-1, w+kx-1, c]  (zero padded)
// blockDim = 192 (192 float4 = 768 floats per k-slot)
// ---------------------------------------------------------------------------
__global__ void im2col_kernel(const float* __restrict__ x1, const float* __restrict__ x2,
                              const float* __restrict__ x3, const float* __restrict__ x4,
                              const float* __restrict__ x5) {
    int m = blockIdx.x;
    int lev = m >> 12;
    int p = m & (NPIX - 1);
    int n = p >> 10;
    int pix = p & 1023;
    int h = pix >> 5, w = pix & 31;

    const float* xn = sel5(lev, x1, x2, x3, x4, x5) + (size_t)n * 1024 * CD;
    size_t arow = (size_t)m * K9;
    int t = threadIdx.x;  // 0..191

    #pragma unroll
    for (int k = 0; k < 9; k++) {
        int hh = h + k / 3 - 1;
        int ww = w + k % 3 - 1;
        bool valid = (hh >= 0) & (hh < HGT) & (ww >= 0) & (ww < WID);
        float4 v = make_float4(0.f, 0.f, 0.f, 0.f);
        if (valid) {
            const float4* s = reinterpret_cast<const float4*>(xn + ((size_t)hh * WID + ww) * CD);
            v = s[t];
        }
        float4* d = reinterpret_cast<float4*>(g_A + arow + (size_t)k * CD);
        d[t] = v;
    }
}

// ---------------------------------------------------------------------------
// Offsets + mask softmax from om rows. One block (256 thr) per pixel.
// ---------------------------------------------------------------------------
__global__ void offmask_kernel(const float* __restrict__ offw, const float* __restrict__ maskw) {
    __shared__ float row[CD];
    __shared__ float res[27];
    int m = blockIdx.x;
    const float* om = g_om + (size_t)m * CD;
    for (int t = threadIdx.x; t < CD; t += 256) row[t] = om[t];
    __syncthreads();

    int warp = threadIdx.x >> 5, lane = threadIdx.x & 31;
    for (int o = warp; o < 27; o += 8) {
        const float* wrow = (o < 18) ? (offw + (size_t)o * CD) : (maskw + (size_t)(o - 18) * CD);
        float s = 0.f;
        for (int t = lane; t < CD; t += 32) s += row[t] * wrow[t];
        #pragma unroll
        for (int d = 16; d > 0; d >>= 1) s += __shfl_xor_sync(0xffffffffu, s, d);
        if (lane == 0) res[o] = s;
    }
    __syncthreads();

    if (threadIdx.x < 18) g_off[(size_t)m * 18 + threadIdx.x] = res[threadIdx.x];
    if (threadIdx.x == 0) {
        float mx = res[18];
        #pragma unroll
        for (int k = 1; k < 9; k++) mx = fmaxf(mx, res[18 + k]);
        float e[9], sum = 0.f;
        #pragma unroll
        for (int k = 0; k < 9; k++) { e[k] = expf(res[18 + k] - mx); sum += e[k]; }
        float inv = 1.f / sum;
        #pragma unroll
        for (int k = 0; k < 9; k++) g_msm[(size_t)m * 9 + k] = e[k] * inv;
    }
}

// ---------------------------------------------------------------------------
// Deformable bilinear sampling * mask  ->  overwrite g_A
// Mask read replicates the reference reshape scramble:
//   mask[n,k,h,w] = softmax_flat[img*9216 + k*1024 + h*32 + w]
// blockDim = 192
// ---------------------------------------------------------------------------
__global__ void sample_kernel(const float* __restrict__ x1, const float* __restrict__ x2,
                              const float* __restrict__ x3, const float* __restrict__ x4,
                              const float* __restrict__ x5) {
    int m = blockIdx.x;
    int lev = m >> 12;
    int p = m & (NPIX - 1);
    int n = p >> 10;
    int pix = p & 1023;
    int h = pix >> 5, w = pix & 31;
    int img = m >> 10;

    const float* xn = sel5(lev, x1, x2, x3, x4, x5) + (size_t)n * 1024 * CD;
    size_t arow = (size_t)m * K9;
    int t = threadIdx.x;  // 0..191

    #pragma unroll
    for (int k = 0; k < 9; k++) {
        float dy = g_off[(size_t)m * 18 + 2 * k];
        float dx = g_off[(size_t)m * 18 + 2 * k + 1];
        float mk = g_msm[(size_t)img * 9216 + (size_t)k * 1024 + pix];

        float py = (float)(h - 1 + k / 3) + dy;
        float px = (float)(w - 1 + k % 3) + dx;
        float fy0 = floorf(py), fx0 = floorf(px);
        int y0 = (int)fy0, x0 = (int)fx0;
        float wy1 = py - fy0, wx1 = px - fx0;
        float wy0 = 1.f - wy1, wx0 = 1.f - wx1;

        float wt[4] = { wy0 * wx0, wy0 * wx1, wy1 * wx0, wy1 * wx1 };
        const float4* ptr[4];
        #pragma unroll
        for (int cy = 0; cy < 2; cy++) {
            #pragma unroll
            for (int cx = 0; cx < 2; cx++) {
                int ci = cy * 2 + cx;
                int yy = y0 + cy, xx = x0 + cx;
                bool valid = (yy >= 0) & (yy < HGT) & (xx >= 0) & (xx < WID);
                if (!valid) wt[ci] = 0.f;
                int yc = min(max(yy, 0), HGT - 1);
                int xc = min(max(xx, 0), WID - 1);
                ptr[ci] = reinterpret_cast<const float4*>(xn + ((size_t)yc * WID + xc) * CD);
                wt[ci] *= mk;
            }
        }
        float4* d = reinterpret_cast<float4*>(g_A + arow + (size_t)k * CD);
        float4 v0 = ptr[0][t], v1 = ptr[1][t], v2 = ptr[2][t], v3 = ptr[3][t];
        float4 o;
        o.x = wt[0] * v0.x + wt[1] * v1.x + wt[2] * v2.x + wt[3] * v3.x;
        o.y = wt[0] * v0.y + wt[1] * v1.y + wt[2] * v2.y + wt[3] * v3.y;
        o.z = wt[0] * v0.z + wt[1] * v1.z + wt[2] * v2.z + wt[3] * v3.z;
        o.w = wt[0] * v0.w + wt[1] * v1.w + wt[2] * v2.w + wt[3] * v3.w;
        d[t] = o;
    }
}

// ---------------------------------------------------------------------------
// TF32 tensor-core GEMM:  C[M,N] = A[M,K] * B[K,N]  (+ epilogue)
// A is split at column ksplit: cols [0,ksplit) from A1 (lda1), [ksplit,K) from
// A2 (lda2, local col = col - ksplit). ksplit and 768 are multiples of 16 so a
// float4 staging load never straddles the split.
// Block tile 128x128, 8 warps each 32x64 (2x8 mma m16n8k8 tiles), K-chunk 16,
// double-buffered smem. REQUIRES: M%128==0, K%16==0, ldb >= grid.x*128.
// C stores guarded by Nc.
// modes: 0: +bias[n]   1: relu((v+bias)*scale+shift)   2: +addsrc[m*ldc+n]
// ---------------------------------------------------------------------------
__global__ __launch_bounds__(256, 2)
void gemm_tf32_kernel(const float* __restrict__ A1, int lda1,
                      const float* __restrict__ A2, int lda2, int ksplit,
                      const float* __restrict__ B, int ldb,
                      float* __restrict__ Cc, int ldc, int Nc,
                      int K, int mode,
                      const float* __restrict__ bias,
                      const float* __restrict__ scale,
                      const float* __restrict__ shift,
                      const float* __restrict__ addsrc) {
    __shared__ __align__(16) float As[2][128][20];   // [m][k], stride 20 -> conflict-free frag reads
    __shared__ __align__(16) float Bs[2][16][136];   // [k][n], stride 136 -> conflict-free frag reads

    const int tid  = threadIdx.x;
    const int lane = tid & 31;
    const int warp = tid >> 5;
    const int gid  = lane >> 2;   // 0..7
    const int tg   = lane & 3;    // 0..3
    const int wm   = warp >> 1;   // 0..3  (m band of 32)
    const int wn   = warp & 1;    // 0..1  (n band of 64)
    const int m0   = blockIdx.y * 128;
    const int n0   = blockIdx.x * 128;

    // staging thread mapping
    const int ar = tid >> 2;          // 0..63   (A row)
    const int ac = (tid & 3) * 4;     // 0,4,8,12 (A k offset)
    const int br = tid >> 5;          // 0..7    (B k row)
    const int bc = (tid & 31) * 4;    // 0..124  (B n offset)

    float4 aS0, aS1, bS0, bS1;

    auto gload = [&](int kc) {
        int col = kc + ac;
        const float* Ap;
        int lc, ld;
        if (col < ksplit) { Ap = A1; lc = col; ld = lda1; }
        else              { Ap = A2; lc = col - ksplit; ld = lda2; }
        aS0 = *reinterpret_cast<const float4*>(&Ap[(size_t)(m0 + ar) * ld + lc]);
        aS1 = *reinterpret_cast<const float4*>(&Ap[(size_t)(m0 + ar + 64) * ld + lc]);
        bS0 = *reinterpret_cast<const float4*>(&B[(size_t)(kc + br) * ldb + n0 + bc]);
        bS1 = *reinterpret_cast<const float4*>(&B[(size_t)(kc + br + 8) * ldb + n0 + bc]);
    };
    auto sstore = [&](int buf) {
        *reinterpret_cast<float4*>(&As[buf][ar][ac])      = tf32r4(aS0);
        *reinterpret_cast<float4*>(&As[buf][ar + 64][ac]) = tf32r4(aS1);
        *reinterpret_cast<float4*>(&Bs[buf][br][bc])      = tf32r4(bS0);
        *reinterpret_cast<float4*>(&Bs[buf][br + 8][bc])  = tf32r4(bS1);
    };

    float acc[2][8][4];
    #pragma unroll
    for (int i = 0; i < 2; i++)
        #pragma unroll
        for (int j = 0; j < 8; j++)
            #pragma unroll
            for (int q = 0; q < 4; q++) acc[i][j][q] = 0.f;

    const int nT = K / 16;
    gload(0);
    sstore(0);
    __syncthreads();

    for (int t = 0; t < nT; t++) {
        const int cur = t & 1;
        if (t + 1 < nT) gload((t + 1) * 16);

        #pragma unroll
        for (int ks = 0; ks < 2; ks++) {
            const int kb = ks * 8;
            uint32_t af[2][4];
            uint32_t bf[8][2];
            #pragma unroll
            for (int mt = 0; mt < 2; mt++) {
                const int mr = wm * 32 + mt * 16 + gid;
                af[mt][0] = __float_as_uint(As[cur][mr][kb + tg]);
                af[mt][1] = __float_as_uint(As[cur][mr + 8][kb + tg]);
                af[mt][2] = __float_as_uint(As[cur][mr][kb + tg + 4]);
                af[mt][3] = __float_as_uint(As[cur][mr + 8][kb + tg + 4]);
            }
            #pragma unroll
            for (int nt = 0; nt < 8; nt++) {
                const int nc = wn * 64 + nt * 8 + gid;
                bf[nt][0] = __float_as_uint(Bs[cur][kb + tg][nc]);
                bf[nt][1] = __float_as_uint(Bs[cur][kb + tg + 4][nc]);
            }
            #pragma unroll
            for (int mt = 0; mt < 2; mt++)
                #pragma unroll
                for (int nt = 0; nt < 8; nt++) {
                    asm volatile(
                        "mma.sync.aligned.m16n8k8.row.col.f32.tf32.tf32.f32 "
                        "{%0,%1,%2,%3}, {%4,%5,%6,%7}, {%8,%9}, {%0,%1,%2,%3};\n"
                        : "+f"(acc[mt][nt][0]), "+f"(acc[mt][nt][1]),
                          "+f"(acc[mt][nt][2]), "+f"(acc[mt][nt][3])
                        : "r"(af[mt][0]), "r"(af[mt][1]), "r"(af[mt][2]), "r"(af[mt][3]),
                          "r"(bf[nt][0]), "r"(bf[nt][1]));
                }
        }

        if (t + 1 < nT) sstore(cur ^ 1);
        __syncthreads();
    }

    // epilogue
    #pragma unroll
    for (int mt = 0; mt < 2; mt++) {
        const int r0 = m0 + wm * 32 + mt * 16 + gid;
        #pragma unroll
        for (int nt = 0; nt < 8; nt++) {
            const int c0 = n0 + wn * 64 + nt * 8 + 2 * tg;
            #pragma unroll
            for (int q = 0; q < 4; q++) {
                const int r = r0 + (q >> 1) * 8;
                const int c = c0 + (q & 1);
                if (c >= Nc) continue;
                float v = acc[mt][nt][q];
                size_t ci = (size_t)r * ldc + c;
                if (mode == 0) {
                    v += bias[c];
                } else if (mode == 1) {
                    v = (v + bias[c]) * scale[c] + shift[c];
                    v = fmaxf(v, 0.f);
                } else {
                    v += addsrc[ci];
                }
                Cc[ci] = v;
            }
        }
    }
}

// ---------------------------------------------------------------------------
extern "C" void kernel_launch(void* const* d_in, const int* in_sizes, int n_in,
                              void* d_out, int out_size) {
    const float* x[5];
    for (int i = 0; i < 5; i++) x[i] = (const float*)d_in[i];
    const float* conv_w   = (const float*)d_in[5];
    const float* conv_b   = (const float*)d_in[6];
    const float* offset_w = (const float*)d_in[7];
    const float* mask_w   = (const float*)d_in[8];
    const float* bn_gamma = (const float*)d_in[9];
    const float* bn_beta  = (const float*)d_in[10];
    const float* bn_mean  = (const float*)d_in[11];
    const float* bn_var   = (const float*)d_in[12];
    const float* wo[8];
    for (int i = 0; i < 8; i++) wo[i] = (const float*)d_in[13 + i];
    float* out = (float*)d_out;

    void *pA_, *pWb_, *pWh_, *pOm_, *pY_, *pScale_, *pShift_;
    cudaGetSymbolAddress(&pA_, g_A);
    cudaGetSymbolAddress(&pWb_, g_Wb);
    cudaGetSymbolAddress(&pWh_, g_Wh);
    cudaGetSymbolAddress(&pOm_, g_om);
    cudaGetSymbolAddress(&pY_, g_y);
    cudaGetSymbolAddress(&pScale_, g_scale);
    cudaGetSymbolAddress(&pShift_, g_shift);
    float* pA = (float*)pA_;
    float* pWb = (float*)pWb_;
    float* pWh = (float*)pWh_;
    float* pOm = (float*)pOm_;
    float* pY = (float*)pY_;
    const float* pScale = (const float*)pScale_;
    const float* pShift = (const float*)pShift_;

    // 0. weight packing + BN prep
    pack_kernel<<<(K9 * CD + 255) / 256, 256>>>(conv_w);
    pack_head_kernel<<<(5 * WHK * WHN + 255) / 256, 256>>>(wo[0], wo[1], wo[2], wo[3],
                                                           wo[4], wo[5], wo[6], wo[7]);
    bnprep_kernel<<<(CD + 255) / 256, 256>>>(bn_gamma, bn_beta, bn_mean, bn_var);

    // 1. im2col (all 5 levels)
    im2col_kernel<<<MTOT, 192>>>(x[0], x[1], x[2], x[3], x[4]);

    // 2. GEMM1 (TF32): om = A * Wb + conv_b     (M=20480, N=768, K=6912)
    {
        dim3 grid(CD / 128, MTOT / 128);
        gemm_tf32_kernel<<<grid, 256>>>(pA, K9, pA, K9, K9, pWb, CD, pOm, CD, CD,
                                        K9, 0, conv_b, nullptr, nullptr, nullptr);
    }

    // 3. offsets + mask softmax
    offmask_kernel<<<MTOT, 256>>>(offset_w, mask_w);

    // 4. deformable sampling -> overwrite g_A
    sample_kernel<<<MTOT, 192>>>(x[0], x[1], x[2], x[3], x[4]);

    // 5. GEMM2 (TF32): y = relu((A * Wb + conv_b) * scale + shift)
    {
        dim3 grid(CD / 128, MTOT / 128);
        gemm_tf32_kernel<<<grid, 256>>>(pA, K9, pA, K9, K9, pWb, CD, pY, CD, CD,
                                        K9, 1, conv_b, pScale, pShift, nullptr);
    }

    // 6. head GEMMs (TF32): per level i,
    //    out[:, off_i : off_i+ch_i] = [y_i | x_i] @ Wh_i + x5[:, off_i : ...]
    //    (Wh zero-padded: levels 0/1 have zero x-half and zero cols >= ch_i)
    static const int ch[5]  = { 30, 100, 150, 220, 268 };
    static const int off[5] = { 0, 30, 130, 280, 500 };

    for (int i = 0; i < 5; i++) {
        dim3 grid((ch[i] + 127) / 128, NPIX / 128);
        gemm_tf32_kernel<<<grid, 256>>>(pY + (size_t)i * NPIX * CD, CD,
                                        x[i], CD, CD,
                                        pWh + (size_t)i * WHK * WHN, WHN,
                                        out + off[i], CD, ch[i],
                                        WHK, 2,
                                        nullptr, nullptr, nullptr,
                                        x[4] + off[i]);
    }
}

// round 7
// speedup vs baseline: 1.4466x; 1.4466x over previous
#include <cuda_runtime.h>
#include <math.h>
#include <stdint.h>

// Problem constants
#define CD    768
#define K9    6912        // 9 * 768
#define HGT   32
#define WID   32
#define NPIX  4096        // per level: 4*32*32
#define MTOT  20480       // 5 * 4096
#define WHK   1536        // head GEMM K (y | x concat)
#define WHN   384         // head GEMM padded N (3 tiles of 128)

// ---------------------------------------------------------------------------
// Scratch (device globals — allocation in kernel_launch is forbidden)
// ---------------------------------------------------------------------------
__device__ __align__(16) float g_A[(size_t)MTOT * K9];    // sampled deformable features (566 MB)
__device__ __align__(16) float g_y[(size_t)MTOT * CD];    // deform block output
__device__ __align__(16) float g_Wb[(size_t)K9 * CD];     // packed weights: Wb[(k*768+c)*768+o] = conv_w[o,c,k]
__device__ __align__(16) float g_Wf[(size_t)K9 * 128];    // folded offset/mask weights [kc][o], o padded 27->128
__device__ __align__(16) float g_biasf[128];              // folded bias (27 used)
__device__ __align__(16) float g_Wh[5 * WHK * WHN];       // packed head weights [lev][k][n], zero padded
__device__ __align__(16) float g_lg[(size_t)MTOT * 32];   // offset/mask logits per pixel (27 used, ldc=32)
__device__ float g_off[MTOT * 18];                        // per pixel: dy0,dx0,dy1,dx1,...
__device__ float g_msm[MTOT * 9];                         // softmax(mask logits), pixel-major, k innermost
__device__ float g_scale[CD];
__device__ float g_shift[CD];

// ---------------------------------------------------------------------------
__device__ __forceinline__ const float* sel5(int i, const float* a, const float* b,
                                             const float* c, const float* d, const float* e) {
    switch (i) { case 0: return a; case 1: return b; case 2: return c; case 3: return d; default: return e; }
}

__device__ __forceinline__ float tf32r(float x) {
    float y;
    asm("cvt.rna.tf32.f32 %0, %1;" : "=f"(y) : "f"(x));
    return y;
}
__device__ __forceinline__ float4 tf32r4(float4 v) {
    v.x = tf32r(v.x); v.y = tf32r(v.y); v.z = tf32r(v.z); v.w = tf32r(v.w);
    return v;
}

// Gather one float4 of the virtual im2col matrix row m, tap offset (dh,dw), channel c.
__device__ __forceinline__ float4 gatherA(int m, int dh, int dw, int c,
                                          const float* x1, const float* x2, const float* x3,
                                          const float* x4, const float* x5) {
    int lev = m >> 12;
    int p = m & (NPIX - 1);
    int n = p >> 10;
    int pix = p & 1023;
    int h = pix >> 5, w = pix & 31;
    int hh = h + dh, ww = w + dw;
    if (hh < 0 || hh >= HGT || ww < 0 || ww >= WID)
        return make_float4(0.f, 0.f, 0.f, 0.f);
    const float* xn = sel5(lev, x1, x2, x3, x4, x5);
    return *reinterpret_cast<const float4*>(xn + ((size_t)n * 1024 + hh * WID + ww) * CD + c);
}

// ---------------------------------------------------------------------------
// Pack conv weights into GEMM-B layout (used by GEMM2 and the fold)
// ---------------------------------------------------------------------------
__global__ void pack_kernel(const float* __restrict__ cw) {
    int i = blockIdx.x * 256 + threadIdx.x;
    if (i >= K9 * CD) return;
    int o = i % CD;
    int kc = i / CD;
    int c = kc % CD;
    int k = kc / CD;
    g_Wb[i] = cw[((size_t)o * CD + c) * 9 + k];
}

// ---------------------------------------------------------------------------
// Fold offset/mask projections into the conv weights:
//   Wf[kc][o] = sum_ch Wb[kc][ch] * proj[o][ch]   (o<18: offset_w, o>=18: mask_w)
// Block K9 computes the folded bias from conv_b instead.
// ---------------------------------------------------------------------------
__global__ void fold_kernel(const float* __restrict__ offw, const float* __restrict__ maskw,
                            const float* __restrict__ convb) {
    __shared__ float row[CD];
    __shared__ float res[27];
    int kc = blockIdx.x;
    const float* src = (kc < K9) ? (g_Wb + (size_t)kc * CD) : convb;
    for (int t = threadIdx.x; t < CD; t += 256) row[t] = src[t];
    __syncthreads();

    int warp = threadIdx.x >> 5, lane = threadIdx.x & 31;
    for (int o = warp; o < 27; o += 8) {
        const float* wrow = (o < 18) ? (offw + (size_t)o * CD) : (maskw + (size_t)(o - 18) * CD);
        float s = 0.f;
        for (int t = lane; t < CD; t += 32) s += row[t] * wrow[t];
        #pragma unroll
        for (int d = 16; d > 0; d >>= 1) s += __shfl_xor_sync(0xffffffffu, s, d);
        if (lane == 0) res[o] = s;
    }
    __syncthreads();

    float* dst = (kc < K9) ? (g_Wf + (size_t)kc * 128) : g_biasf;
    for (int t = threadIdx.x; t < 128; t += 256) dst[t] = (t < 27) ? res[t] : 0.f;
}

// Pack head weights: g_Wh[lev][k][n] = (k<768 ? wa[n][k] : wb[n][k-768]), 0 beyond ch or missing wb
__global__ void pack_head_kernel(const float* __restrict__ w1, const float* __restrict__ w2,
                                 const float* __restrict__ w3a, const float* __restrict__ w3b,
                                 const float* __restrict__ w4a, const float* __restrict__ w4b,
                                 const float* __restrict__ w5a, const float* __restrict__ w5b) {
    int i = blockIdx.x * 256 + threadIdx.x;
    if (i >= 5 * WHK * WHN) return;
    int lev = i / (WHK * WHN);
    int rem = i % (WHK * WHN);
    int k = rem / WHN;
    int n = rem % WHN;

    const int chs[5] = { 30, 100, 150, 220, 268 };
    const float* wa;
    const float* wb;
    switch (lev) {
        case 0: wa = w1;  wb = nullptr; break;
        case 1: wa = w2;  wb = nullptr; break;
        case 2: wa = w3a; wb = w3b;     break;
        case 3: wa = w4a; wb = w4b;     break;
        default: wa = w5a; wb = w5b;    break;
    }
    float v = 0.f;
    if (n < chs[lev]) {
        if (k < CD) v = wa[(size_t)n * CD + k];
        else if (wb != nullptr) v = wb[(size_t)n * CD + (k - CD)];
    }
    g_Wh[i] = v;
}

__global__ void bnprep_kernel(const float* __restrict__ g, const float* __restrict__ be,
                              const float* __restrict__ mu, const float* __restrict__ var) {
    int i = blockIdx.x * 256 + threadIdx.x;
    if (i < CD) {
        float inv = g[i] / sqrtf(var[i] + 1e-5f);
        g_scale[i] = inv;
        g_shift[i] = be[i] - mu[i] * inv;
    }
}

// ---------------------------------------------------------------------------
// Split logits -> offsets + softmax(mask). One thread per pixel.
// ---------------------------------------------------------------------------
__global__ void offsplit_kernel() {
    int m = blockIdx.x * 256 + threadIdx.x;
    if (m >= MTOT) return;
    const float* lg = g_lg + (size_t)m * 32;
    #pragma unroll
    for (int o = 0; o < 18; o++) g_off[(size_t)m * 18 + o] = lg[o];
    float mx = lg[18];
    #pragma unroll
    for (int k = 1; k < 9; k++) mx = fmaxf(mx, lg[18 + k]);
    float e[9], sum = 0.f;
    #pragma unroll
    for (int k = 0; k < 9; k++) { e[k] = expf(lg[18 + k] - mx); sum += e[k]; }
    float inv = 1.f / sum;
    #pragma unroll
    for (int k = 0; k < 9; k++) g_msm[(size_t)m * 9 + k] = e[k] * inv;
}

// ---------------------------------------------------------------------------
// Deformable bilinear sampling * mask  ->  write g_A
// Mask read replicates the reference reshape scramble:
//   mask[n,k,h,w] = softmax_flat[img*9216 + k*1024 + h*32 + w]
// blockDim = 192
// ---------------------------------------------------------------------------
__global__ void sample_kernel(const float* __restrict__ x1, const float* __restrict__ x2,
                              const float* __restrict__ x3, const float* __restrict__ x4,
                              const float* __restrict__ x5) {
    int m = blockIdx.x;
    int lev = m >> 12;
    int p = m & (NPIX - 1);
    int n = p >> 10;
    int pix = p & 1023;
    int h = pix >> 5, w = pix & 31;
    int img = m >> 10;

    const float* xn = sel5(lev, x1, x2, x3, x4, x5) + (size_t)n * 1024 * CD;
    size_t arow = (size_t)m * K9;
    int t = threadIdx.x;  // 0..191

    #pragma unroll
    for (int k = 0; k < 9; k++) {
        float dy = g_off[(size_t)m * 18 + 2 * k];
        float dx = g_off[(size_t)m * 18 + 2 * k + 1];
        float mk = g_msm[(size_t)img * 9216 + (size_t)k * 1024 + pix];

        float py = (float)(h - 1 + k / 3) + dy;
        float px = (float)(w - 1 + k % 3) + dx;
        float fy0 = floorf(py), fx0 = floorf(px);
        int y0 = (int)fy0, x0 = (int)fx0;
        float wy1 = py - fy0, wx1 = px - fx0;
        float wy0 = 1.f - wy1, wx0 = 1.f - wx1;

        float wt[4] = { wy0 * wx0, wy0 * wx1, wy1 * wx0, wy1 * wx1 };
        const float4* ptr[4];
        #pragma unroll
        for (int cy = 0; cy < 2; cy++) {
            #pragma unroll
            for (int cx = 0; cx < 2; cx++) {
                int ci = cy * 2 + cx;
                int yy = y0 + cy, xx = x0 + cx;
                bool valid = (yy >= 0) & (yy < HGT) & (xx >= 0) & (xx < WID);
                if (!valid) wt[ci] = 0.f;
                int yc = min(max(yy, 0), HGT - 1);
                int xc = min(max(xx, 0), WID - 1);
                ptr[ci] = reinterpret_cast<const float4*>(xn + ((size_t)yc * WID + xc) * CD);
                wt[ci] *= mk;
            }
        }
        float4* d = reinterpret_cast<float4*>(g_A + arow + (size_t)k * CD);
        float4 v0 = ptr[0][t], v1 = ptr[1][t], v2 = ptr[2][t], v3 = ptr[3][t];
        float4 o;
        o.x = wt[0] * v0.x + wt[1] * v1.x + wt[2] * v2.x + wt[3] * v3.x;
        o.y = wt[0] * v0.y + wt[1] * v1.y + wt[2] * v2.y + wt[3] * v3.y;
        o.z = wt[0] * v0.z + wt[1] * v1.z + wt[2] * v2.z + wt[3] * v3.z;
        o.w = wt[0] * v0.w + wt[1] * v1.w + wt[2] * v2.w + wt[3] * v3.w;
        d[t] = o;
    }
}

// ---------------------------------------------------------------------------
// TF32 tensor-core GEMM:  C[M,N] = A[M,K] * B[K,N]  (+ epilogue)
// GATHERA=0: A is split at column ksplit: cols [0,ksplit) from A1 (lda1),
//            [ksplit,K) from A2 (lda2, local col = col - ksplit).
// GATHERA=1: A rows are virtual im2col rows gathered from x1..x5 (A1/A2 unused).
//            768 % 16 == 0, so a 16-wide chunk never straddles a tap.
// Block tile 128x128, 8 warps each 32x64 (2x8 mma m16n8k8 tiles), K-chunk 16,
// double-buffered smem. REQUIRES: M%128==0, K%16==0, ldb >= grid.x*128.
// C stores guarded by Nc.
// modes: 0: +bias[n]   1: relu((v+bias)*scale+shift)   2: +addsrc[m*ldc+n]
// ---------------------------------------------------------------------------
template <int GATHERA>
__global__ __launch_bounds__(256, 2)
void gemm_tf32_kernel(const float* __restrict__ A1, int lda1,
                      const float* __restrict__ A2, int lda2, int ksplit,
                      const float* __restrict__ B, int ldb,
                      float* __restrict__ Cc, int ldc, int Nc,
                      int K, int mode,
                      const float* __restrict__ bias,
                      const float* __restrict__ scale,
                      const float* __restrict__ shift,
                      const float* __restrict__ addsrc,
                      const float* __restrict__ x1, const float* __restrict__ x2,
                      const float* __restrict__ x3, const float* __restrict__ x4,
                      const float* __restrict__ x5) {
    __shared__ __align__(16) float As[2][128][20];   // [m][k], stride 20 -> conflict-free frag reads
    __shared__ __align__(16) float Bs[2][16][136];   // [k][n], stride 136 -> conflict-free frag reads

    const int tid  = threadIdx.x;
    const int lane = tid & 31;
    const int warp = tid >> 5;
    const int gid  = lane >> 2;   // 0..7
    const int tg   = lane & 3;    // 0..3
    const int wm   = warp >> 1;   // 0..3  (m band of 32)
    const int wn   = warp & 1;    // 0..1  (n band of 64)
    const int m0   = blockIdx.y * 128;
    const int n0   = blockIdx.x * 128;

    // staging thread mapping
    const int ar = tid >> 2;          // 0..63   (A row)
    const int ac = (tid & 3) * 4;     // 0,4,8,12 (A k offset)
    const int br = tid >> 5;          // 0..7    (B k row)
    const int bc = (tid & 31) * 4;    // 0..124  (B n offset)

    float4 aS0, aS1, bS0, bS1;

    auto gload = [&](int kc) {
        int col = kc + ac;
        if (GATHERA) {
            int tap = col / CD;
            int c = col - tap * CD;
            int dh = tap / 3 - 1, dw = tap % 3 - 1;
            aS0 = gatherA(m0 + ar, dh, dw, c, x1, x2, x3, x4, x5);
            aS1 = gatherA(m0 + ar + 64, dh, dw, c, x1, x2, x3, x4, x5);
        } else {
            const float* Ap;
            int lc, ld;
            if (col < ksplit) { Ap = A1; lc = col; ld = lda1; }
            else              { Ap = A2; lc = col - ksplit; ld = lda2; }
            aS0 = *reinterpret_cast<const float4*>(&Ap[(size_t)(m0 + ar) * ld + lc]);
            aS1 = *reinterpret_cast<const float4*>(&Ap[(size_t)(m0 + ar + 64) * ld + lc]);
        }
        bS0 = *reinterpret_cast<const float4*>(&B[(size_t)(kc + br) * ldb + n0 + bc]);
        bS1 = *reinterpret_cast<const float4*>(&B[(size_t)(kc + br + 8) * ldb + n0 + bc]);
    };
    auto sstore = [&](int buf) {
        *reinterpret_cast<float4*>(&As[buf][ar][ac])      = tf32r4(aS0);
        *reinterpret_cast<float4*>(&As[buf][ar + 64][ac]) = tf32r4(aS1);
        *reinterpret_cast<float4*>(&Bs[buf][br][bc])      = tf32r4(bS0);
        *reinterpret_cast<float4*>(&Bs[buf][br + 8][bc])  = tf32r4(bS1);
    };

    float acc[2][8][4];
    #pragma unroll
    for (int i = 0; i < 2; i++)
        #pragma unroll
        for (int j = 0; j < 8; j++)
            #pragma unroll
            for (int q = 0; q < 4; q++) acc[i][j][q] = 0.f;

    const int nT = K / 16;
    gload(0);
    sstore(0);
    __syncthreads();

    for (int t = 0; t < nT; t++) {
        const int cur = t & 1;
        if (t + 1 < nT) gload((t + 1) * 16);

        #pragma unroll
        for (int ks = 0; ks < 2; ks++) {
            const int kb = ks * 8;
            uint32_t af[2][4];
            uint32_t bf[8][2];
            #pragma unroll
            for (int mt = 0; mt < 2; mt++) {
                const int mr = wm * 32 + mt * 16 + gid;
                af[mt][0] = __float_as_uint(As[cur][mr][kb + tg]);
                af[mt][1] = __float_as_uint(As[cur][mr + 8][kb + tg]);
                af[mt][2] = __float_as_uint(As[cur][mr][kb + tg + 4]);
                af[mt][3] = __float_as_uint(As[cur][mr + 8][kb + tg + 4]);
            }
            #pragma unroll
            for (int nt = 0; nt < 8; nt++) {
                const int nc = wn * 64 + nt * 8 + gid;
                bf[nt][0] = __float_as_uint(Bs[cur][kb + tg][nc]);
                bf[nt][1] = __float_as_uint(Bs[cur][kb + tg + 4][nc]);
            }
            #pragma unroll
            for (int mt = 0; mt < 2; mt++)
                #pragma unroll
                for (int nt = 0; nt < 8; nt++) {
                    asm volatile(
                        "mma.sync.aligned.m16n8k8.row.col.f32.tf32.tf32.f32 "
                        "{%0,%1,%2,%3}, {%4,%5,%6,%7}, {%8,%9}, {%0,%1,%2,%3};\n"
                        : "+f"(acc[mt][nt][0]), "+f"(acc[mt][nt][1]),
                          "+f"(acc[mt][nt][2]), "+f"(acc[mt][nt][3])
                        : "r"(af[mt][0]), "r"(af[mt][1]), "r"(af[mt][2]), "r"(af[mt][3]),
                          "r"(bf[nt][0]), "r"(bf[nt][1]));
                }
        }

        if (t + 1 < nT) sstore(cur ^ 1);
        __syncthreads();
    }

    // epilogue
    #pragma unroll
    for (int mt = 0; mt < 2; mt++) {
        const int r0 = m0 + wm * 32 + mt * 16 + gid;
        #pragma unroll
        for (int nt = 0; nt < 8; nt++) {
            const int c0 = n0 + wn * 64 + nt * 8 + 2 * tg;
            #pragma unroll
            for (int q = 0; q < 4; q++) {
                const int r = r0 + (q >> 1) * 8;
                const int c = c0 + (q & 1);
                if (c >= Nc) continue;
                float v = acc[mt][nt][q];
                size_t ci = (size_t)r * ldc + c;
                if (mode == 0) {
                    v += bias[c];
                } else if (mode == 1) {
                    v = (v + bias[c]) * scale[c] + shift[c];
                    v = fmaxf(v, 0.f);
                } else {
                    v += addsrc[ci];
                }
                Cc[ci] = v;
            }
        }
    }
}

// ---------------------------------------------------------------------------
extern "C" void kernel_launch(void* const* d_in, const int* in_sizes, int n_in,
                              void* d_out, int out_size) {
    const float* x[5];
    for (int i = 0; i < 5; i++) x[i] = (const float*)d_in[i];
    const float* conv_w   = (const float*)d_in[5];
    const float* conv_b   = (const float*)d_in[6];
    const float* offset_w = (const float*)d_in[7];
    const float* mask_w   = (const float*)d_in[8];
    const float* bn_gamma = (const float*)d_in[9];
    const float* bn_beta  = (const float*)d_in[10];
    const float* bn_mean  = (const float*)d_in[11];
    const float* bn_var   = (const float*)d_in[12];
    const float* wo[8];
    for (int i = 0; i < 8; i++) wo[i] = (const float*)d_in[13 + i];
    float* out = (float*)d_out;

    void *pA_, *pWb_, *pWf_, *pBf_, *pWh_, *pLg_, *pY_, *pScale_, *pShift_;
    cudaGetSymbolAddress(&pA_, g_A);
    cudaGetSymbolAddress(&pWb_, g_Wb);
    cudaGetSymbolAddress(&pWf_, g_Wf);
    cudaGetSymbolAddress(&pBf_, g_biasf);
    cudaGetSymbolAddress(&pWh_, g_Wh);
    cudaGetSymbolAddress(&pLg_, g_lg);
    cudaGetSymbolAddress(&pY_, g_y);
    cudaGetSymbolAddress(&pScale_, g_scale);
    cudaGetSymbolAddress(&pShift_, g_shift);
    float* pA = (float*)pA_;
    float* pWf = (float*)pWf_;
    float* pWh = (float*)pWh_;
    float* pLg = (float*)pLg_;
    float* pY = (float*)pY_;
    float* pWb = (float*)pWb_;
    const float* pBf = (const float*)pBf_;
    const float* pScale = (const float*)pScale_;
    const float* pShift = (const float*)pShift_;

    // 0. weight packing + fold + BN prep
    pack_kernel<<<(K9 * CD + 255) / 256, 256>>>(conv_w);
    fold_kernel<<<K9 + 1, 256>>>(offset_w, mask_w, conv_b);
    pack_head_kernel<<<(5 * WHK * WHN + 255) / 256, 256>>>(wo[0], wo[1], wo[2], wo[3],
                                                           wo[4], wo[5], wo[6], wo[7]);
    bnprep_kernel<<<(CD + 255) / 256, 256>>>(bn_gamma, bn_beta, bn_mean, bn_var);

    // 1. logits GEMM (TF32, gather-A from x, im2col-free):
    //    lg = im2col(x) * Wf + biasf    (M=20480, N=27(pad128), K=6912)
    {
        dim3 grid(1, MTOT / 128);
        gemm_tf32_kernel<1><<<grid, 256>>>(nullptr, 0, nullptr, 0, 0,
                                           pWf, 128, pLg, 32, 27,
                                           K9, 0, pBf, nullptr, nullptr, nullptr,
                                           x[0], x[1], x[2], x[3], x[4]);
    }

    // 2. split logits -> offsets + mask softmax
    offsplit_kernel<<<(MTOT + 255) / 256, 256>>>();

    // 3. deformable sampling -> write g_A
    sample_kernel<<<MTOT, 192>>>(x[0], x[1], x[2], x[3], x[4]);

    // 4. GEMM2 (TF32): y = relu((A * Wb + conv_b) * scale + shift)
    {
        dim3 grid(CD / 128, MTOT / 128);
        gemm_tf32_kernel<0><<<grid, 256>>>(pA, K9, pA, K9, K9, pWb, CD, pY, CD, CD,
                                           K9, 1, conv_b, pScale, pShift, nullptr,
                                           nullptr, nullptr, nullptr, nullptr, nullptr);
    }

    // 5. head GEMMs (TF32): per level i,
    //    out[:, off_i : off_i+ch_i] = [y_i | x_i] @ Wh_i + x5[:, off_i : ...]
    //    (Wh zero-padded: levels 0/1 have zero x-half and zero cols >= ch_i)
    static const int ch[5]  = { 30, 100, 150, 220, 268 };
    static const int off[5] = { 0, 30, 130, 280, 500 };

    for (int i = 0; i < 5; i++) {
        dim3 grid((ch[i] + 127) / 128, NPIX / 128);
        gemm_tf32_kernel<0><<<grid, 256>>>(pY + (size_t)i * NPIX * CD, CD,
                                           x[i], CD, CD,
                                           pWh + (size_t)i * WHK * WHN, WHN,
                                           out + off[i], CD, ch[i],
                                           WHK, 2,
                                           nullptr, nullptr, nullptr,
                                           x[4] + off[i],
                                           nullptr, nullptr, nullptr, nullptr, nullptr);
    }
}